// round 5
// baseline (speedup 1.0000x reference)
#include <cuda_runtime.h>

// VanillaRNN B=128,S=2048,E=256,H=512,V=128 fp32 — persistent kernel v2.
// 128 CTAs (4 row-groups x 32 col-groups). Per CTA: 32 B-rows x 16 H-cols of
// the recurrence + 4 V-cols of the output projection.
// Round-4 changes vs v1:
//  - 8x8 thread microtile via column-pair f32x2, k-split 32 (lane = k-slice)
//  - weights k-major in SMEM with XOR swizzles -> conflict-free LDS
//  - Wfc slice in registers (loaded once); V-proj reuses rec h loads
//  - input projection computed in barrier slack, pre-reduced into xacc
//  - barrier scoped to 32-CTA row groups (4 independent counters)

#define Bb   128
#define Ss   2048
#define Vv   128
#define Ee   256
#define Hh   512
#define NBLK 128
#define NTHR 256

#define RR_STRIDE 516       // floats per k-slice row of rec/X partials
#define RV_STRIDE 132       // floats per k-slice row of V partials

// SMEM offsets (floats)
#define OFF_SH   0                       // h tile: 32 x 512 (unit-swizzled)
#define OFF_WH   16384                   // WhT k-major: 512 x 16 (swizzled)
#define OFF_WX   24576                   // WxT k-major: 256 x 16 (swizzled)
#define OFF_RR   28672                   // rec/X partials: 32 x 516
#define OFF_RV   45184                   // V partials: 32 x 132
#define OFF_TMP  49408                   // 256 x float4 reduce scratch
#define OFF_XA   50432                   // xacc: 512
#define OFF_BH   50944                   // 16 (bh + bx)
#define OFF_BFC  50960                   // 4
#define OFF_TOK  50964                   // 32 ints
#define SMEM_FLOATS 50996
#define SMEM_BYTES  (SMEM_FLOATS * 4)

__device__ float g_h[2][Bb * Hh];        // double-buffered hidden state
__device__ int   g_bar4[4 * 32];         // per-row-group counters, 128B apart

static __device__ __forceinline__ float2 ffma2(float2 a, float2 b, float2 c) {
    union { float2 f; unsigned long long u; } A, B2, C;
    A.f = a; B2.f = b; C.f = c;
    asm("fma.rn.f32x2 %0, %1, %2, %0;" : "+l"(C.u) : "l"(A.u), "l"(B2.u));
    return C.f;
}
// 16B-unit swizzles (keep lanes on distinct 16B positions mod 128B)
static __device__ __forceinline__ int swz_h (int u) { return u ^ ((u >> 3) & 7); }
static __device__ __forceinline__ int swz_wh(int u) { return u ^ ((u >> 6) & 7); }
static __device__ __forceinline__ int swz_wx(int u) { return u ^ ((u >> 5) & 7); }

__global__ void rnn_init_kernel() {
    int idx = blockIdx.x * blockDim.x + threadIdx.x;
    for (int i = idx; i < Bb * Hh; i += gridDim.x * blockDim.x)
        g_h[1][i] = 0.0f;                  // h_{-1} = 0 (read at t=0)
    if (idx < 4 * 32) g_bar4[idx] = 0;
}

// Input projection for the NEXT step: compute xe@Wx partials, reduce into xacc.
// Called uniformly by all 256 threads (contains __syncthreads).
static __device__ __forceinline__ void inproj_phase(
    float* sm, const float* __restrict__ emb,
    int tid, int ks, int rowg, int colg)
{
    const int* stok = (const int*)(sm + OFF_TOK);
    float2 ax[8][4];
#pragma unroll
    for (int r = 0; r < 8; ++r)
#pragma unroll
        for (int q = 0; q < 4; ++q) ax[r][q] = make_float2(0.f, 0.f);
    int tok[8];
#pragma unroll
    for (int r = 0; r < 8; ++r) tok[r] = stok[rowg * 8 + r];
    const float4* wx4 = (const float4*)(sm + OFF_WX);
#pragma unroll
    for (int m = 0; m < 2; ++m) {
        const int e0 = ks * 8 + m * 4;
        float4 xe[8];
#pragma unroll
        for (int r = 0; r < 8; ++r)
            xe[r] = __ldg((const float4*)(emb + tok[r] * Ee + e0));
#pragma unroll
        for (int ki = 0; ki < 4; ++ki) {
            const int u = (e0 + ki) * 4 + colg * 2;
            const float4 wa = wx4[swz_wx(u)];
            const float4 wb = wx4[swz_wx(u + 1)];
#pragma unroll
            for (int r = 0; r < 8; ++r) {
                const float hv = ((const float*)&xe[r])[ki];
                const float2 hh = make_float2(hv, hv);
                ax[r][0] = ffma2(hh, make_float2(wa.x, wa.y), ax[r][0]);
                ax[r][1] = ffma2(hh, make_float2(wa.z, wa.w), ax[r][1]);
                ax[r][2] = ffma2(hh, make_float2(wb.x, wb.y), ax[r][2]);
                ax[r][3] = ffma2(hh, make_float2(wb.z, wb.w), ax[r][3]);
            }
        }
    }
#pragma unroll
    for (int r = 0; r < 8; ++r) {
        const int o = (rowg * 8 + r) * 16 + colg * 8;
        float* dst = sm + OFF_RR + ks * RR_STRIDE + o;
        *(float4*)dst       = make_float4(ax[r][0].x, ax[r][0].y, ax[r][1].x, ax[r][1].y);
        *(float4*)(dst + 4) = make_float4(ax[r][2].x, ax[r][2].y, ax[r][3].x, ax[r][3].y);
    }
    __syncthreads();
    {
        const int half = tid >> 7, o4 = tid & 127;
        float4 ssum = make_float4(0.f, 0.f, 0.f, 0.f);
#pragma unroll
        for (int s = 0; s < 16; ++s) {
            const float4 v = *(const float4*)(sm + OFF_RR + (half * 16 + s) * RR_STRIDE + o4 * 4);
            ssum.x += v.x; ssum.y += v.y; ssum.z += v.z; ssum.w += v.w;
        }
        *(float4*)(sm + OFF_TMP + tid * 4) = ssum;
    }
    __syncthreads();
    if (tid < 128) {
        float4 a = *(const float4*)(sm + OFF_TMP + tid * 4);
        const float4 b = *(const float4*)(sm + OFF_TMP + (tid + 128) * 4);
        a.x += b.x; a.y += b.y; a.z += b.z; a.w += b.w;
        *(float4*)(sm + OFF_XA + tid * 4) = a;   // read later by same thread
    }
}

__global__ void __launch_bounds__(NTHR, 1)
rnn_persistent(const int*   __restrict__ x,
               const float* __restrict__ emb,
               const float* __restrict__ Wx,
               const float* __restrict__ bx,
               const float* __restrict__ Wh,
               const float* __restrict__ bh,
               const float* __restrict__ Wfc,
               const float* __restrict__ bfc,
               float* __restrict__ out)
{
    extern __shared__ float sm[];
    const int tid  = threadIdx.x;
    const int bidx = blockIdx.x;
    const int rgc  = bidx >> 5;          // CTA row-group 0..3 (32 B-rows)
    const int R0   = rgc << 5;
    const int cg   = bidx & 31;
    const int C0   = cg << 4;            // 16 H-cols
    const int VC0  = cg << 2;            // 4 V-cols
    // thread mapping: lane = k-slice, warp = (rowg, colg) tile
    const int ks   = tid & 31;           // k-slice: rec k in [ks*16, ks*16+16)
    const int rc   = tid >> 5;
    const int rowg = rc >> 1;            // rows rowg*8 .. +7
    const int colg = rc & 1;             // cols colg*8 .. +7 (of 16)
    int* bar = &g_bar4[rgc * 32];

    // ---- prologue: stage weights (k-major, swizzled) -------------------
    for (int idx = tid; idx < Hh * 16; idx += NTHR) {
        const int k = idx >> 4, c = idx & 15;
        const int u = idx >> 2, l = idx & 3;
        sm[OFF_WH + swz_wh(u) * 4 + l] = Wh[k * Hh + C0 + c];
    }
    for (int idx = tid; idx < Ee * 16; idx += NTHR) {
        const int k = idx >> 4, c = idx & 15;
        const int u = idx >> 2, l = idx & 3;
        sm[OFF_WX + swz_wx(u) * 4 + l] = Wx[k * Hh + C0 + c];
    }
    float2 wf[16];                       // Wfc slice: 2 V-cols x 16 k, in regs
#pragma unroll
    for (int kk = 0; kk < 16; ++kk) {
        const int k = ks * 16 + kk;
        wf[kk] = *(const float2*)(Wfc + k * Vv + VC0 + colg * 2);
    }
    if (tid < 16) sm[OFF_BH + tid]  = bh[C0 + tid] + bx[C0 + tid];
    if (tid < 4)  sm[OFF_BFC + tid] = bfc[VC0 + tid];
    if (tid < 32) ((int*)(sm + OFF_TOK))[tid] = x[(R0 + tid) * Ss + 0];
    __syncthreads();
    inproj_phase(sm, emb, tid, ks, rowg, colg);   // xacc for t=0

    const float4* wh4 = (const float4*)(sm + OFF_WH);

    for (int t = 0; t <= Ss; ++t) {
        // ---- wait for h(t-1) from the 32 CTAs of this row group --------
        if (t > 0) {
            if (tid == 0) {
                const int target = t << 5;
                int v;
                do {
                    asm volatile("ld.acquire.gpu.global.b32 %0, [%1];"
                                 : "=r"(v) : "l"(bar) : "memory");
                    if (v - target >= 0) break;
                    __nanosleep(64);
                } while (true);
            }
            __syncthreads();
        }
        // ---- stage h(t-1) tile from L2 into swizzled SMEM --------------
        const float* hsrc = g_h[(t + 1) & 1];
#pragma unroll
        for (int q = 0; q < 16; ++q) {
            const int g   = tid + (q << 8);
            const int row = g >> 7;
            const int u   = g & 127;
            const float4 v = __ldcg(((const float4*)(hsrc + ((R0 + row) << 9))) + u);
            *(float4*)(sm + OFF_SH + (row << 9) + swz_h(u) * 4) = v;
        }
        __syncthreads();

        float2 accV[8];
#pragma unroll
        for (int r = 0; r < 8; ++r) accV[r] = make_float2(0.f, 0.f);

        if (t < Ss) {
            // prefetch next tokens for the slack-phase input projection
            if (t + 1 < Ss && tid < 32)
                ((int*)(sm + OFF_TOK))[tid] = x[(R0 + tid) * Ss + (t + 1)];

            float2 accR[8][4];
#pragma unroll
            for (int r = 0; r < 8; ++r)
#pragma unroll
                for (int q = 0; q < 4; ++q) accR[r][q] = make_float2(0.f, 0.f);

            // ---- recurrence (K slice of 16) fused with V-proj of h(t-1)
#pragma unroll
            for (int m = 0; m < 4; ++m) {
                const int kb = ks * 16 + m * 4;
                const int u0 = ks * 4 + m;
                float4 h4[8];
#pragma unroll
                for (int r = 0; r < 8; ++r)
                    h4[r] = *(const float4*)(sm + OFF_SH + ((rowg * 8 + r) << 9)
                                             + swz_h(u0) * 4);
#pragma unroll
                for (int ki = 0; ki < 4; ++ki) {
                    const int u = (kb + ki) * 4 + colg * 2;
                    const float4 wa = wh4[swz_wh(u)];
                    const float4 wb = wh4[swz_wh(u + 1)];
                    const float2 wv = wf[m * 4 + ki];
#pragma unroll
                    for (int r = 0; r < 8; ++r) {
                        const float hv = ((const float*)&h4[r])[ki];
                        const float2 hh = make_float2(hv, hv);
                        accR[r][0] = ffma2(hh, make_float2(wa.x, wa.y), accR[r][0]);
                        accR[r][1] = ffma2(hh, make_float2(wa.z, wa.w), accR[r][1]);
                        accR[r][2] = ffma2(hh, make_float2(wb.x, wb.y), accR[r][2]);
                        accR[r][3] = ffma2(hh, make_float2(wb.z, wb.w), accR[r][3]);
                        accV[r]    = ffma2(hh, wv, accV[r]);
                    }
                }
            }
            // rec partial writes
#pragma unroll
            for (int r = 0; r < 8; ++r) {
                const int o = (rowg * 8 + r) * 16 + colg * 8;
                float* dst = sm + OFF_RR + ks * RR_STRIDE + o;
                *(float4*)dst       = make_float4(accR[r][0].x, accR[r][0].y,
                                                  accR[r][1].x, accR[r][1].y);
                *(float4*)(dst + 4) = make_float4(accR[r][2].x, accR[r][2].y,
                                                  accR[r][3].x, accR[r][3].y);
            }
        } else {
            // t == S: output projection of h(S-1) only
#pragma unroll
            for (int m = 0; m < 4; ++m) {
                const int u0 = ks * 4 + m;
                float4 h4[8];
#pragma unroll
                for (int r = 0; r < 8; ++r)
                    h4[r] = *(const float4*)(sm + OFF_SH + ((rowg * 8 + r) << 9)
                                             + swz_h(u0) * 4);
#pragma unroll
                for (int ki = 0; ki < 4; ++ki) {
                    const float2 wv = wf[m * 4 + ki];
#pragma unroll
                    for (int r = 0; r < 8; ++r) {
                        const float hv = ((const float*)&h4[r])[ki];
                        accV[r] = ffma2(make_float2(hv, hv), wv, accV[r]);
                    }
                }
            }
        }
        if (t > 0 || t == 0) { /* V partials written every step; consumed when t>0 */ }
#pragma unroll
        for (int r = 0; r < 8; ++r)
            *(float2*)(sm + OFF_RV + ks * RV_STRIDE + (rowg * 8 + r) * 4 + colg * 2)
                = accV[r];
        __syncthreads();

        // ---- reduce: h(t) = tanh(rec + xacc + bias); out(t-1) = V + bfc
        if (t < Ss) {
            const int half = tid >> 7, o4 = tid & 127;
            float4 ssum = make_float4(0.f, 0.f, 0.f, 0.f);
#pragma unroll
            for (int s = 0; s < 16; ++s) {
                const float4 v = *(const float4*)(sm + OFF_RR
                                    + (half * 16 + s) * RR_STRIDE + o4 * 4);
                ssum.x += v.x; ssum.y += v.y; ssum.z += v.z; ssum.w += v.w;
            }
            *(float4*)(sm + OFF_TMP + tid * 4) = ssum;
        }
        __syncthreads();
        if (t < Ss && tid < 128) {
            float4 a = *(const float4*)(sm + OFF_TMP + tid * 4);
            const float4 b  = *(const float4*)(sm + OFF_TMP + (tid + 128) * 4);
            const float4 xa = *(const float4*)(sm + OFF_XA + tid * 4);
            const int jb = (tid & 3) * 4;
            a.x = tanhf(a.x + b.x + xa.x + sm[OFF_BH + jb + 0]);
            a.y = tanhf(a.y + b.y + xa.y + sm[OFF_BH + jb + 1]);
            a.z = tanhf(a.z + b.z + xa.z + sm[OFF_BH + jb + 2]);
            a.w = tanhf(a.w + b.w + xa.w + sm[OFF_BH + jb + 3]);
            const int i = tid >> 2;
            *(float4*)(&g_h[t & 1][((R0 + i) << 9) + C0 + jb]) = a;
        }
        if (t > 0 && tid >= 128 && tid < 192) {
            const int t2 = tid - 128;               // 0..63 -> one float2 of out
            float2 vs = make_float2(0.f, 0.f);
#pragma unroll
            for (int s = 0; s < 32; ++s) {
                const float2 v = *(const float2*)(sm + OFF_RV + s * RV_STRIDE + t2 * 2);
                vs.x += v.x; vs.y += v.y;
            }
            const int i = t2 >> 1, jc = (t2 & 1) * 2;
            vs.x += sm[OFF_BFC + jc];
            vs.y += sm[OFF_BFC + jc + 1];
            *(float2*)(out + (long)(R0 + i) * (Ss * Vv) + (long)(t - 1) * Vv + VC0 + jc) = vs;
        }

        if (t < Ss) {
            __threadfence();
            __syncthreads();
            if (tid == 0) atomicAdd(bar, 1);         // arrive
            // ---- slack: input projection for step t+1 (hides barrier skew)
            if (t + 1 < Ss) inproj_phase(sm, emb, tid, ks, rowg, colg);
        }
    }
}

extern "C" void kernel_launch(void* const* d_in, const int* in_sizes, int n_in,
                              void* d_out, int out_size) {
    const int*   x   = (const int*)  d_in[0];
    const float* emb = (const float*)d_in[1];
    const float* Wx  = (const float*)d_in[2];
    const float* bx  = (const float*)d_in[3];
    const float* Wh  = (const float*)d_in[4];
    const float* bh  = (const float*)d_in[5];
    const float* Wfc = (const float*)d_in[6];
    const float* bfc = (const float*)d_in[7];
    float* out = (float*)d_out;

    cudaFuncSetAttribute(rnn_persistent,
                         cudaFuncAttributeMaxDynamicSharedMemorySize, SMEM_BYTES);

    rnn_init_kernel<<<64, 256>>>();
    rnn_persistent<<<NBLK, NTHR, SMEM_BYTES>>>(x, emb, Wx, bx, Wh, bh, Wfc, bfc, out);
}

// round 7
// speedup vs baseline: 1.3770x; 1.3770x over previous
#include <cuda_runtime.h>
#include <cstdint>

// VanillaRNN B=128,S=2048,E=256,H=512,V=128 fp32 — persistent kernel v3.
// Round-5/6 changes:
//  - V=128 distinct tokens => precompute g_xw[v] = emb[v]@Wx + bx + bh ONCE
//    (xw_kernel). Per-step input projection becomes a 16B gather in finalize.
//  - inproj machinery deleted -> ~145 regs, no spills, 2 fewer syncs/step.
//  - Wfc slice moved to SMEM (k-unit swizzled, conflict-free).
//  - h tile loaded via cp.async (no register staging).
//  - all rec-loop LDS conflict-free by construction (XOR swizzles).

#define Bb   128
#define Ss   2048
#define Vv   128
#define Ee   256
#define Hh   512
#define NBLK 128
#define NTHR 256

#define RR_STRIDE 516       // Δbank 4 per k-slice row -> conflict-free
#define RV_STRIDE 134       // Δbank 6 per k-slice row -> conflict-free

// SMEM offsets (floats)
#define OFF_SH   0                      // h tile: 32 x 512 (unit-swizzled)
#define OFF_WH   16384                  // WhT k-major: 512 x 16 (swizzled)
#define OFF_WF   24576                  // WfcT: 4 x 512 (k-unit swizzled)
#define OFF_RR   26624                  // rec partials: 32 x 516
#define OFF_RV   43136                  // V partials: 32 x 134
#define OFF_TMP  47424                  // 256 x float4 reduce scratch
#define OFF_BFC  48448                  // 4
#define OFF_TOK  48452                  // 32 ints
#define SMEM_FLOATS 48484
#define SMEM_BYTES  (SMEM_FLOATS * 4)

__device__ float g_h[2][Bb * Hh];       // double-buffered hidden state
__device__ float g_xw[Vv * Hh];         // token -> (emb@Wx + bx + bh)
__device__ int   g_bar4[4 * 32];        // per-row-group counters, 128B apart

static __device__ __forceinline__ float2 ffma2(float2 a, float2 b, float2 c) {
    union { float2 f; unsigned long long u; } A, B2, C;
    A.f = a; B2.f = b; C.f = c;
    asm("fma.rn.f32x2 %0, %1, %2, %0;" : "+l"(C.u) : "l"(A.u), "l"(B2.u));
    return C.f;
}
static __device__ __forceinline__ int swz_h (int u) { return u ^ ((u >> 3) & 7); }
static __device__ __forceinline__ int swz_wh(int u) { return u ^ ((u >> 6) & 7); }

__global__ void rnn_init_kernel() {
    int idx = blockIdx.x * blockDim.x + threadIdx.x;
    for (int i = idx; i < Bb * Hh; i += gridDim.x * blockDim.x)
        g_h[1][i] = 0.0f;               // h_{-1} = 0 (read at t=0)
    if (idx < 4 * 32) g_bar4[idx] = 0;
}

// g_xw[v][:] = emb[v] @ Wx + bx + bh   (tiny one-off GEMM, 128 blocks)
__global__ void __launch_bounds__(512) xw_kernel(
    const float* __restrict__ emb, const float* __restrict__ Wx,
    const float* __restrict__ bx,  const float* __restrict__ bh)
{
    __shared__ float se[Ee];
    const int v = blockIdx.x, j = threadIdx.x;
    if (j < Ee) se[j] = emb[v * Ee + j];
    __syncthreads();
    float acc = 0.f;
#pragma unroll 8
    for (int e = 0; e < Ee; ++e) acc = fmaf(se[e], Wx[e * Hh + j], acc);
    g_xw[v * Hh + j] = acc + bx[j] + bh[j];
}

__global__ void __launch_bounds__(NTHR, 1)
rnn_persistent(const int*   __restrict__ x,
               const float* __restrict__ Wh,
               const float* __restrict__ Wfc,
               const float* __restrict__ bfc,
               float* __restrict__ out)
{
    extern __shared__ float sm[];
    const int tid  = threadIdx.x;
    const int bidx = blockIdx.x;
    const int rgc  = bidx >> 5;          // row-group 0..3 (32 B-rows)
    const int R0   = rgc << 5;
    const int cg   = bidx & 31;
    const int C0   = cg << 4;            // 16 H-cols
    const int VC0  = cg << 2;            // 4 V-cols
    // lane = k-slice (16 k's each); warp = (rowg, colg) 8x8 tile
    const int ks   = tid & 31;
    const int rc   = tid >> 5;
    const int rowg = rc >> 1;            // rows rowg*8 .. +7
    const int colg = rc & 1;             // col pair block: cols colg*8 .. +7
    int* bar = &g_bar4[rgc * 32];
    int* stok = (int*)(sm + OFF_TOK);

    uint32_t smem_u32;
    asm("{ .reg .u64 t0; cvta.to.shared.u64 t0, %1; cvt.u32.u64 %0, t0; }"
        : "=r"(smem_u32) : "l"(sm));

    // ---- prologue: stage Wh (k-major, swizzled) and Wfc slice ----------
    for (int idx = tid; idx < Hh * 16; idx += NTHR) {
        const int k = idx >> 4, c = idx & 15;
        const int u = idx >> 2, l = idx & 3;
        sm[OFF_WH + swz_wh(u) * 4 + l] = Wh[k * Hh + C0 + c];
    }
    for (int idx = tid; idx < 4 * Hh; idx += NTHR) {
        const int c = idx >> 9, k = idx & 511;
        const int u = k >> 2,  l = k & 3;
        sm[OFF_WF + (c << 9) + swz_h(u) * 4 + l] = Wfc[k * Vv + VC0 + c];
    }
    if (tid < 4) sm[OFF_BFC + tid] = bfc[VC0 + tid];

    const float4* wh4 = (const float4*)(sm + OFF_WH);

    for (int t = 0; t <= Ss; ++t) {
        if (t < Ss && tid < 32) stok[tid] = x[(R0 + tid) * Ss + t];
        // ---- wait for h(t-1) from this row group's 32 CTAs -------------
        if (t > 0) {
            if (tid == 0) {
                const int target = t << 5;
                int v;
                do {
                    asm volatile("ld.acquire.gpu.global.b32 %0, [%1];"
                                 : "=r"(v) : "l"(bar) : "memory");
                    if (v - target >= 0) break;
                    __nanosleep(32);
                } while (true);
            }
            __syncthreads();
        }
        // ---- h(t-1) tile -> swizzled SMEM via cp.async -----------------
        const float* hsrc = g_h[(t + 1) & 1];
#pragma unroll
        for (int q = 0; q < 16; ++q) {
            const int g   = tid + (q << 8);
            const int row = g >> 7;
            const int u   = g & 127;
            const uint32_t sa = smem_u32 +
                (uint32_t)((OFF_SH + (row << 9) + swz_h(u) * 4) * 4);
            const float4* ga = ((const float4*)(hsrc + ((R0 + row) << 9))) + u;
            asm volatile("cp.async.cg.shared.global [%0], [%1], 16;"
                         :: "r"(sa), "l"(ga));
        }
        asm volatile("cp.async.commit_group;");
        asm volatile("cp.async.wait_group 0;");
        __syncthreads();

        float2 accV[8];
#pragma unroll
        for (int r = 0; r < 8; ++r) accV[r] = make_float2(0.f, 0.f);

        if (t < Ss) {
            float2 accR[8][4];
#pragma unroll
            for (int r = 0; r < 8; ++r)
#pragma unroll
                for (int q = 0; q < 4; ++q) accR[r][q] = make_float2(0.f, 0.f);

            // ---- recurrence (16 k's) fused with V-proj of h(t-1) -------
#pragma unroll
            for (int m = 0; m < 4; ++m) {
                const int um = swz_h(ks * 4 + m);
                float4 h4[8];
#pragma unroll
                for (int r = 0; r < 8; ++r)
                    h4[r] = *(const float4*)(sm + OFF_SH
                              + ((rowg * 8 + r) << 9) + um * 4);
                const float4 wfa = *(const float4*)(sm + OFF_WF
                              + ((colg * 2 + 0) << 9) + um * 4);
                const float4 wfb = *(const float4*)(sm + OFF_WF
                              + ((colg * 2 + 1) << 9) + um * 4);
#pragma unroll
                for (int ki = 0; ki < 4; ++ki) {
                    const int u  = ks * 64 + (m * 4 + ki) * 4 + colg * 2;
                    const float4 wa = wh4[u ^ (ks & 7)];
                    const float4 wb = wh4[(u + 1) ^ (ks & 7)];
                    const float2 wv = make_float2(((const float*)&wfa)[ki],
                                                  ((const float*)&wfb)[ki]);
#pragma unroll
                    for (int r = 0; r < 8; ++r) {
                        const float hv = ((const float*)&h4[r])[ki];
                        const float2 hh = make_float2(hv, hv);
                        accR[r][0] = ffma2(hh, make_float2(wa.x, wa.y), accR[r][0]);
                        accR[r][1] = ffma2(hh, make_float2(wa.z, wa.w), accR[r][1]);
                        accR[r][2] = ffma2(hh, make_float2(wb.x, wb.y), accR[r][2]);
                        accR[r][3] = ffma2(hh, make_float2(wb.z, wb.w), accR[r][3]);
                        accV[r]    = ffma2(hh, wv, accV[r]);
                    }
                }
            }
#pragma unroll
            for (int r = 0; r < 8; ++r) {
                const int o = (rowg * 8 + r) * 16 + colg * 8;
                float* dst = sm + OFF_RR + ks * RR_STRIDE + o;
                *(float4*)dst       = make_float4(accR[r][0].x, accR[r][0].y,
                                                  accR[r][1].x, accR[r][1].y);
                *(float4*)(dst + 4) = make_float4(accR[r][2].x, accR[r][2].y,
                                                  accR[r][3].x, accR[r][3].y);
            }
        } else {
            // t == S: output projection of h(S-1) only
#pragma unroll
            for (int m = 0; m < 4; ++m) {
                const int um = swz_h(ks * 4 + m);
                const float4 wfa = *(const float4*)(sm + OFF_WF
                              + ((colg * 2 + 0) << 9) + um * 4);
                const float4 wfb = *(const float4*)(sm + OFF_WF
                              + ((colg * 2 + 1) << 9) + um * 4);
#pragma unroll
                for (int r = 0; r < 8; ++r) {
                    const float4 h4 = *(const float4*)(sm + OFF_SH
                              + ((rowg * 8 + r) << 9) + um * 4);
#pragma unroll
                    for (int ki = 0; ki < 4; ++ki) {
                        const float hv = ((const float*)&h4)[ki];
                        const float2 wv = make_float2(((const float*)&wfa)[ki],
                                                      ((const float*)&wfb)[ki]);
                        accV[r] = ffma2(make_float2(hv, hv), wv, accV[r]);
                    }
                }
            }
        }
#pragma unroll
        for (int r = 0; r < 8; ++r)
            *(float2*)(sm + OFF_RV + ks * RV_STRIDE
                       + (rowg * 8 + r) * 4 + colg * 2) = accV[r];
        __syncthreads();

        // ---- stage-1 reduce over 16 of 32 k-slices ---------------------
        if (t < Ss) {
            const int half = tid >> 7, o4 = tid & 127;
            float4 ssum = make_float4(0.f, 0.f, 0.f, 0.f);
#pragma unroll
            for (int s = 0; s < 16; ++s) {
                const float4 v = *(const float4*)(sm + OFF_RR
                                    + (half * 16 + s) * RR_STRIDE + o4 * 4);
                ssum.x += v.x; ssum.y += v.y; ssum.z += v.z; ssum.w += v.w;
            }
            *(float4*)(sm + OFF_TMP + tid * 4) = ssum;
        }
        __syncthreads();

        // ---- finalize: h(t) = tanh(rec + xw[token]); out(t-1) ----------
        if (t < Ss && tid < 128) {
            const int i = tid >> 2, jb = (tid & 3) * 4;
            const float4 xa = __ldg((const float4*)(g_xw + stok[i] * Hh + C0 + jb));
            float4 a = *(const float4*)(sm + OFF_TMP + tid * 4);
            const float4 b = *(const float4*)(sm + OFF_TMP + (tid + 128) * 4);
            a.x = tanhf(a.x + b.x + xa.x);
            a.y = tanhf(a.y + b.y + xa.y);
            a.z = tanhf(a.z + b.z + xa.z);
            a.w = tanhf(a.w + b.w + xa.w);
            *(float4*)(&g_h[t & 1][((R0 + i) << 9) + C0 + jb]) = a;
        }
        if (t > 0 && tid >= 128 && tid < 192) {
            const int t2 = tid - 128;            // one float2 of out
            float2 vs = make_float2(0.f, 0.f);
#pragma unroll
            for (int s = 0; s < 32; ++s) {
                const float2 v = *(const float2*)(sm + OFF_RV
                                    + s * RV_STRIDE + t2 * 2);
                vs.x += v.x; vs.y += v.y;
            }
            const int i = t2 >> 1, jc = (t2 & 1) * 2;
            vs.x += sm[OFF_BFC + jc];
            vs.y += sm[OFF_BFC + jc + 1];
            *(float2*)(out + (long)(R0 + i) * (Ss * Vv)
                       + (long)(t - 1) * Vv + VC0 + jc) = vs;
        }

        // ---- arrive ----------------------------------------------------
        if (t < Ss) {
            __threadfence();
            __syncthreads();
            if (tid == 0) atomicAdd(bar, 1);
        }
    }
}

extern "C" void kernel_launch(void* const* d_in, const int* in_sizes, int n_in,
                              void* d_out, int out_size) {
    const int*   x   = (const int*)  d_in[0];
    const float* emb = (const float*)d_in[1];
    const float* Wx  = (const float*)d_in[2];
    const float* bx  = (const float*)d_in[3];
    const float* Wh  = (const float*)d_in[4];
    const float* bh  = (const float*)d_in[5];
    const float* Wfc = (const float*)d_in[6];
    const float* bfc = (const float*)d_in[7];
    float* out = (float*)d_out;

    cudaFuncSetAttribute(rnn_persistent,
                         cudaFuncAttributeMaxDynamicSharedMemorySize, SMEM_BYTES);

    rnn_init_kernel<<<64, 256>>>();
    xw_kernel<<<Vv, 512>>>(emb, Wx, bx, bh);
    rnn_persistent<<<NBLK, NTHR, SMEM_BYTES>>>(x, Wh, Wfc, bfc, out);
}

// round 8
// speedup vs baseline: 1.5851x; 1.1511x over previous
#include <cuda_runtime.h>
#include <cstdint>

// VanillaRNN B=128,S=2048,E=256,H=512,V=128 fp32 — persistent kernel v4.
// Round-7 changes (critical-path trim):
//  - arrive uses red.release.gpu (no separate __threadfence)
//  - single-stage 256-thread float2 reduce (TMP stage removed)
//  - g_xw gather prefetched at loop top (hidden under rec compute)
//  - V-partials + out reduce moved AFTER arrive (off inter-CTA path)
//  - tight poll (no nanosleep)

#define Bb   128
#define Ss   2048
#define Vv   128
#define Ee   256
#define Hh   512
#define NBLK 128
#define NTHR 256

#define RR_STRIDE 516       // Δbank 4 per k-slice row -> conflict-free
#define RV_STRIDE 134       // Δbank 6 per k-slice row -> conflict-free

// SMEM offsets (floats)
#define OFF_SH   0                      // h tile: 32 x 512 (unit-swizzled)
#define OFF_WH   16384                  // WhT k-major: 512 x 16 (swizzled)
#define OFF_WF   24576                  // WfcT: 4 x 512 (k-unit swizzled)
#define OFF_RR   26624                  // rec partials: 32 x 516
#define OFF_RV   43136                  // V partials: 32 x 134
#define OFF_BFC  47424                  // 4
#define OFF_TOK  47428                  // 32 ints
#define SMEM_FLOATS 47460
#define SMEM_BYTES  (SMEM_FLOATS * 4)

__device__ float g_h[2][Bb * Hh];       // double-buffered hidden state
__device__ float g_xw[Vv * Hh];         // token -> (emb@Wx + bx + bh)
__device__ int   g_bar4[4 * 32];        // per-row-group counters, 128B apart

static __device__ __forceinline__ float2 ffma2(float2 a, float2 b, float2 c) {
    union { float2 f; unsigned long long u; } A, B2, C;
    A.f = a; B2.f = b; C.f = c;
    asm("fma.rn.f32x2 %0, %1, %2, %0;" : "+l"(C.u) : "l"(A.u), "l"(B2.u));
    return C.f;
}
static __device__ __forceinline__ int swz_h (int u) { return u ^ ((u >> 3) & 7); }
static __device__ __forceinline__ int swz_wh(int u) { return u ^ ((u >> 6) & 7); }

__global__ void rnn_init_kernel() {
    int idx = blockIdx.x * blockDim.x + threadIdx.x;
    for (int i = idx; i < Bb * Hh; i += gridDim.x * blockDim.x)
        g_h[1][i] = 0.0f;               // h_{-1} = 0 (read at t=0)
    if (idx < 4 * 32) g_bar4[idx] = 0;
}

// g_xw[v][:] = emb[v] @ Wx + bx + bh   (tiny one-off GEMM, 128 blocks)
__global__ void __launch_bounds__(512) xw_kernel(
    const float* __restrict__ emb, const float* __restrict__ Wx,
    const float* __restrict__ bx,  const float* __restrict__ bh)
{
    __shared__ float se[Ee];
    const int v = blockIdx.x, j = threadIdx.x;
    if (j < Ee) se[j] = emb[v * Ee + j];
    __syncthreads();
    float acc = 0.f;
#pragma unroll 8
    for (int e = 0; e < Ee; ++e) acc = fmaf(se[e], Wx[e * Hh + j], acc);
    g_xw[v * Hh + j] = acc + bx[j] + bh[j];
}

__global__ void __launch_bounds__(NTHR, 1)
rnn_persistent(const int*   __restrict__ x,
               const float* __restrict__ Wh,
               const float* __restrict__ Wfc,
               const float* __restrict__ bfc,
               float* __restrict__ out)
{
    extern __shared__ float sm[];
    const int tid  = threadIdx.x;
    const int bidx = blockIdx.x;
    const int rgc  = bidx >> 5;          // row-group 0..3 (32 B-rows)
    const int R0   = rgc << 5;
    const int cg   = bidx & 31;
    const int C0   = cg << 4;            // 16 H-cols
    const int VC0  = cg << 2;            // 4 V-cols
    // lane = k-slice (16 k's each); warp = (rowg, colg) 8x8 tile
    const int ks   = tid & 31;
    const int rc   = tid >> 5;
    const int rowg = rc >> 1;            // rows rowg*8 .. +7
    const int colg = rc & 1;             // col pair block: cols colg*8 .. +7
    int* bar = &g_bar4[rgc * 32];
    int* stok = (int*)(sm + OFF_TOK);
    // finalize mapping: thread tid owns h-output float2 at (row i2, col j2)
    const int i2 = tid >> 3;
    const int j2 = (tid & 7) * 2;

    uint32_t smem_u32;
    asm("{ .reg .u64 t0; cvta.to.shared.u64 t0, %1; cvt.u32.u64 %0, t0; }"
        : "=r"(smem_u32) : "l"(sm));

    // ---- prologue: stage Wh (k-major, swizzled) and Wfc slice ----------
    for (int idx = tid; idx < Hh * 16; idx += NTHR) {
        const int k = idx >> 4, c = idx & 15;
        const int u = idx >> 2, l = idx & 3;
        sm[OFF_WH + swz_wh(u) * 4 + l] = Wh[k * Hh + C0 + c];
    }
    for (int idx = tid; idx < 4 * Hh; idx += NTHR) {
        const int c = idx >> 9, k = idx & 511;
        const int u = k >> 2,  l = k & 3;
        sm[OFF_WF + (c << 9) + swz_h(u) * 4 + l] = Wfc[k * Vv + VC0 + c];
    }
    if (tid < 4) sm[OFF_BFC + tid] = bfc[VC0 + tid];

    const float4* wh4 = (const float4*)(sm + OFF_WH);

    for (int t = 0; t <= Ss; ++t) {
        if (t < Ss && tid < 32) stok[tid] = x[(R0 + tid) * Ss + t];
        // ---- wait for h(t-1) from this row group's 32 CTAs -------------
        if (t > 0) {
            if (tid == 0) {
                const int target = t << 5;
                int v;
                do {
                    asm volatile("ld.acquire.gpu.global.b32 %0, [%1];"
                                 : "=r"(v) : "l"(bar) : "memory");
                } while (v - target < 0);
            }
            __syncthreads();
        }
        // ---- h(t-1) tile -> swizzled SMEM via cp.async -----------------
        const float* hsrc = g_h[(t + 1) & 1];
#pragma unroll
        for (int q = 0; q < 16; ++q) {
            const int g   = tid + (q << 8);
            const int row = g >> 7;
            const int u   = g & 127;
            const uint32_t sa = smem_u32 +
                (uint32_t)((OFF_SH + (row << 9) + swz_h(u) * 4) * 4);
            const float4* ga = ((const float4*)(hsrc + ((R0 + row) << 9))) + u;
            asm volatile("cp.async.cg.shared.global [%0], [%1], 16;"
                         :: "r"(sa), "l"(ga));
        }
        asm volatile("cp.async.commit_group;");
        asm volatile("cp.async.wait_group 0;");
        __syncthreads();

        // ---- prefetch xw[token] for this step's finalize (hidden) ------
        float2 xa = make_float2(0.f, 0.f);
        if (t < Ss)
            xa = __ldg((const float2*)(g_xw + stok[i2] * Hh + C0 + j2));

        float2 accV[8];
#pragma unroll
        for (int r = 0; r < 8; ++r) accV[r] = make_float2(0.f, 0.f);

        if (t < Ss) {
            float2 accR[8][4];
#pragma unroll
            for (int r = 0; r < 8; ++r)
#pragma unroll
                for (int q = 0; q < 4; ++q) accR[r][q] = make_float2(0.f, 0.f);

            // ---- recurrence (16 k's) fused with V-proj of h(t-1) -------
#pragma unroll
            for (int m = 0; m < 4; ++m) {
                const int um = swz_h(ks * 4 + m);
                float4 h4[8];
#pragma unroll
                for (int r = 0; r < 8; ++r)
                    h4[r] = *(const float4*)(sm + OFF_SH
                              + ((rowg * 8 + r) << 9) + um * 4);
                const float4 wfa = *(const float4*)(sm + OFF_WF
                              + ((colg * 2 + 0) << 9) + um * 4);
                const float4 wfb = *(const float4*)(sm + OFF_WF
                              + ((colg * 2 + 1) << 9) + um * 4);
#pragma unroll
                for (int ki = 0; ki < 4; ++ki) {
                    const int u  = ks * 64 + (m * 4 + ki) * 4 + colg * 2;
                    const float4 wa = wh4[u ^ (ks & 7)];
                    const float4 wb = wh4[(u + 1) ^ (ks & 7)];
                    const float2 wv = make_float2(((const float*)&wfa)[ki],
                                                  ((const float*)&wfb)[ki]);
#pragma unroll
                    for (int r = 0; r < 8; ++r) {
                        const float hv = ((const float*)&h4[r])[ki];
                        const float2 hh = make_float2(hv, hv);
                        accR[r][0] = ffma2(hh, make_float2(wa.x, wa.y), accR[r][0]);
                        accR[r][1] = ffma2(hh, make_float2(wa.z, wa.w), accR[r][1]);
                        accR[r][2] = ffma2(hh, make_float2(wb.x, wb.y), accR[r][2]);
                        accR[r][3] = ffma2(hh, make_float2(wb.z, wb.w), accR[r][3]);
                        accV[r]    = ffma2(hh, wv, accV[r]);
                    }
                }
            }
#pragma unroll
            for (int r = 0; r < 8; ++r) {
                const int o = (rowg * 8 + r) * 16 + colg * 8;
                float* dst = sm + OFF_RR + ks * RR_STRIDE + o;
                *(float4*)dst       = make_float4(accR[r][0].x, accR[r][0].y,
                                                  accR[r][1].x, accR[r][1].y);
                *(float4*)(dst + 4) = make_float4(accR[r][2].x, accR[r][2].y,
                                                  accR[r][3].x, accR[r][3].y);
            }
            __syncthreads();

            // ---- single-stage reduce (256 thr x float2) + tanh + publish
            float2 s = xa;
#pragma unroll
            for (int sidx = 0; sidx < 32; ++sidx) {
                const float2 v = *(const float2*)(sm + OFF_RR
                                    + sidx * RR_STRIDE + tid * 2);
                s.x += v.x; s.y += v.y;
            }
            s.x = tanhf(s.x);
            s.y = tanhf(s.y);
            *(float2*)(&g_h[t & 1][((R0 + i2) << 9) + C0 + j2]) = s;
            __syncthreads();
            if (tid == 0)
                asm volatile("red.release.gpu.global.add.s32 [%0], %1;"
                             :: "l"(bar), "r"(1) : "memory");
        } else {
            // t == S: output projection of h(S-1) only
#pragma unroll
            for (int m = 0; m < 4; ++m) {
                const int um = swz_h(ks * 4 + m);
                const float4 wfa = *(const float4*)(sm + OFF_WF
                              + ((colg * 2 + 0) << 9) + um * 4);
                const float4 wfb = *(const float4*)(sm + OFF_WF
                              + ((colg * 2 + 1) << 9) + um * 4);
#pragma unroll
                for (int r = 0; r < 8; ++r) {
                    const float4 h4 = *(const float4*)(sm + OFF_SH
                              + ((rowg * 8 + r) << 9) + um * 4);
#pragma unroll
                    for (int ki = 0; ki < 4; ++ki) {
                        const float hv = ((const float*)&h4)[ki];
                        const float2 wv = make_float2(((const float*)&wfa)[ki],
                                                      ((const float*)&wfb)[ki]);
                        accV[r] = ffma2(make_float2(hv, hv), wv, accV[r]);
                    }
                }
            }
        }

        // ---- OFF the inter-CTA critical path: out(t-1) -----------------
        if (t > 0) {
#pragma unroll
            for (int r = 0; r < 8; ++r)
                *(float2*)(sm + OFF_RV + ks * RV_STRIDE
                           + (rowg * 8 + r) * 4 + colg * 2) = accV[r];
            __syncthreads();
            if (tid < 128) {
                float s = sm[OFF_BFC + (tid & 3)];
#pragma unroll
                for (int sidx = 0; sidx < 32; ++sidx)
                    s += sm[OFF_RV + sidx * RV_STRIDE + tid];
                out[(long)(R0 + (tid >> 2)) * (Ss * Vv)
                    + (long)(t - 1) * Vv + VC0 + (tid & 3)] = s;
            }
        }
    }
}

extern "C" void kernel_launch(void* const* d_in, const int* in_sizes, int n_in,
                              void* d_out, int out_size) {
    const int*   x   = (const int*)  d_in[0];
    const float* emb = (const float*)d_in[1];
    const float* Wx  = (const float*)d_in[2];
    const float* bx  = (const float*)d_in[3];
    const float* Wh  = (const float*)d_in[4];
    const float* bh  = (const float*)d_in[5];
    const float* Wfc = (const float*)d_in[6];
    const float* bfc = (const float*)d_in[7];
    float* out = (float*)d_out;

    cudaFuncSetAttribute(rnn_persistent,
                         cudaFuncAttributeMaxDynamicSharedMemorySize, SMEM_BYTES);

    rnn_init_kernel<<<64, 256>>>();
    xw_kernel<<<Vv, 512>>>(emb, Wx, bx, bh);
    rnn_persistent<<<NBLK, NTHR, SMEM_BYTES>>>(x, Wh, Wfc, bfc, out);
}